// round 9
// baseline (speedup 1.0000x reference)
#include <cuda_runtime.h>
#include <math.h>
#include <cstdint>

#define TT 128
#define BB 1024
#define HH 256
#define G4 1024
#define TB (TT*BB)

typedef unsigned long long u64;

// ---------------- scratch (allocation-free) ----------------
__device__ float g_bufA[(size_t)TB*HH];
__device__ float g_bufB[(size_t)TB*HH];
__device__ float g_bufC[(size_t)TB*HH];
__device__ float g_A0[(size_t)TB*G4];     // u@Wih0^T + bih0 + bhh0
__device__ float g_state[6*BB*HH];        // h0[2], h1[2], c0, c1
__device__ float g_bias1[G4];             // bih1 + bhh1
__device__ float g_bias0[G4];             // bih0 + bhh0
__device__ unsigned g_bar;                // grid barrier arrive counter
__device__ unsigned g_phase_ctr;          // grid barrier phase counter

// ---------------- f32x2 helpers (fp32 out-MLP SGEMM) ----------------
__device__ __forceinline__ void fma2(u64 &d, u64 a, u64 b) {
    asm("fma.rn.f32x2 %0, %1, %2, %0;" : "+l"(d) : "l"(a), "l"(b));
}
__device__ __forceinline__ u64 dup2(float x) {
    u64 r; asm("mov.b64 %0, {%1, %1};" : "=l"(r) : "f"(x)); return r;
}
__device__ __forceinline__ float lo32(u64 v) {
    float f; asm("{ .reg .b32 t; mov.b64 {%0, t}, %1; }" : "=f"(f) : "l"(v)); return f;
}
__device__ __forceinline__ float hi32(u64 v) {
    float f; asm("{ .reg .b32 t; mov.b64 {t, %0}, %1; }" : "=f"(f) : "l"(v)); return f;
}

// ---------------- tf32 / activation helpers ----------------
__device__ __forceinline__ uint32_t tf32r(float x) {
    uint32_t r; asm("cvt.rna.tf32.f32 %0, %1;" : "=r"(r) : "f"(x)); return r;
}
__device__ __forceinline__ float tanhfast(float x) {
    float r; asm("tanh.approx.f32 %0, %1;" : "=f"(r) : "f"(x)); return r;
}
__device__ __forceinline__ float sigfast(float x) {
    return fmaf(tanhfast(0.5f * x), 0.5f, 0.5f);
}
__device__ __forceinline__ void mma_tf32(float* d, const uint32_t* a, const uint32_t* b) {
    asm volatile(
        "mma.sync.aligned.m16n8k8.row.col.f32.tf32.tf32.f32 "
        "{%0,%1,%2,%3}, {%4,%5,%6,%7}, {%8,%9}, {%0,%1,%2,%3};"
        : "+f"(d[0]), "+f"(d[1]), "+f"(d[2]), "+f"(d[3])
        : "r"(a[0]), "r"(a[1]), "r"(a[2]), "r"(a[3]), "r"(b[0]), "r"(b[1]));
}
__device__ __forceinline__ float4 ldcg4(const float* p) {
    return __ldcg((const float4*)p);
}

// ---------------- grid barrier (128 CTAs) ----------------
__device__ __forceinline__ void gsync(unsigned* lp, int tid) {
    __syncthreads();
    if (tid == 0) {
        __threadfence();
        unsigned old = atomicAdd(&g_bar, 1u);
        if (old == 127u) {
            g_bar = 0u;
            __threadfence();
            atomicAdd(&g_phase_ctr, 1u);
        } else {
            while (*(volatile unsigned*)&g_phase_ctr <= *lp) __nanosleep(64);
        }
    }
    (*lp)++;
    __syncthreads();
}

// ---------------- small kernels ----------------
__global__ void zero6(float* s) {
    int i = blockIdx.x * blockDim.x + threadIdx.x;
    ((float4*)s)[i] = make_float4(0.f, 0.f, 0.f, 0.f);
    if (i == 0) { g_bar = 0u; g_phase_ctr = 0u; }
}
__global__ void bias_comb(const float* a, const float* b, float* o) {
    int i = blockIdx.x * blockDim.x + threadIdx.x;
    o[i] = a[i] + b[i];
}
__global__ void in_mlp1(const float* __restrict__ x, const float* __restrict__ W,
                        const float* __restrict__ b, float* __restrict__ out) {
    int idx = blockIdx.x * blockDim.x + threadIdx.x;
    int m = idx >> 8, n = idx & 255;
    const float* xr = x + m * 6;
    const float* wr = W + n * 6;
    float s = b[n];
#pragma unroll
    for (int k = 0; k < 6; k++) s = fmaf(xr[k], wr[k], s);
    out[idx] = fmaxf(s, 0.f);
}

// ---------------- smem config ----------------
#define KCH 64
#define APAD 68
#define AS_F (64*APAD)
#define BS_F (128*APAD)
#define SMEM_MMA ((2*AS_F + 2*BS_F)*4)

// ---------------- generic tf32 mma GEMM: C = act(A@B^T + bias) ----------------
__global__ __launch_bounds__(256, 1) void gemm_mma(
    int N, int K,
    const float* __restrict__ A, const float* __restrict__ B,
    const float* __restrict__ bias, float* __restrict__ C, int do_relu)
{
    extern __shared__ float sdyn[];
    int tid = threadIdx.x;
    int lane = tid & 31, wid = tid >> 5;
    int wm = wid >> 2, wn = wid & 3;
    int gid = lane >> 2, tidg = lane & 3;
    int n0 = blockIdx.x << 7;
    int m0 = blockIdx.y << 6;

    float acc[2][4][4];
#pragma unroll
    for (int mt = 0; mt < 2; mt++)
#pragma unroll
        for (int g = 0; g < 4; g++)
#pragma unroll
            for (int q = 0; q < 4; q++) acc[mt][g][q] = 0.f;

    int CH = K >> 6;
    int arow = tid >> 4, akq = (tid & 15) << 2;
    float4 ra[4], rb[8];

#pragma unroll
    for (int i = 0; i < 4; i++)
        ra[i] = *(const float4*)(A + (size_t)(m0 + arow + i * 16) * K + akq);
#pragma unroll
    for (int i = 0; i < 8; i++)
        rb[i] = *(const float4*)(B + (size_t)(n0 + arow + i * 16) * K + akq);
#pragma unroll
    for (int i = 0; i < 4; i++) {
        uint4 v = make_uint4(tf32r(ra[i].x), tf32r(ra[i].y), tf32r(ra[i].z), tf32r(ra[i].w));
        *(uint4*)&sdyn[(arow + i * 16) * APAD + akq] = v;
    }
#pragma unroll
    for (int i = 0; i < 8; i++) {
        uint4 v = make_uint4(tf32r(rb[i].x), tf32r(rb[i].y), tf32r(rb[i].z), tf32r(rb[i].w));
        *(uint4*)&sdyn[2 * AS_F + (arow + i * 16) * APAD + akq] = v;
    }

    for (int c = 0; c < CH; c++) {
        __syncthreads();
        int buf = c & 1;
        if (c + 1 < CH) {
            int kb = (c + 1) << 6;
#pragma unroll
            for (int i = 0; i < 4; i++)
                ra[i] = *(const float4*)(A + (size_t)(m0 + arow + i * 16) * K + kb + akq);
#pragma unroll
            for (int i = 0; i < 8; i++)
                rb[i] = *(const float4*)(B + (size_t)(n0 + arow + i * 16) * K + kb + akq);
        }
        const float* Ab = sdyn + buf * AS_F;
        const float* Bb = sdyn + 2 * AS_F + buf * BS_F;
#pragma unroll
        for (int kk = 0; kk < 8; kk++) {
            int k = kk * 8;
            uint32_t af[2][4];
#pragma unroll
            for (int mt = 0; mt < 2; mt++) {
                int rbase = wm * 32 + mt * 16;
                af[mt][0] = __float_as_uint(Ab[(rbase + gid) * APAD + k + tidg]);
                af[mt][1] = __float_as_uint(Ab[(rbase + gid + 8) * APAD + k + tidg]);
                af[mt][2] = __float_as_uint(Ab[(rbase + gid) * APAD + k + tidg + 4]);
                af[mt][3] = __float_as_uint(Ab[(rbase + gid + 8) * APAD + k + tidg + 4]);
            }
            uint32_t bf[4][2];
#pragma unroll
            for (int g = 0; g < 4; g++) {
                int n = g * 32 + wn * 8 + gid;
                bf[g][0] = __float_as_uint(Bb[n * APAD + k + tidg]);
                bf[g][1] = __float_as_uint(Bb[n * APAD + k + tidg + 4]);
            }
#pragma unroll
            for (int mt = 0; mt < 2; mt++)
#pragma unroll
                for (int g = 0; g < 4; g++)
                    mma_tf32(acc[mt][g], af[mt], bf[g]);
        }
        if (c + 1 < CH) {
            int nbuf = (c + 1) & 1;
#pragma unroll
            for (int i = 0; i < 4; i++) {
                uint4 v = make_uint4(tf32r(ra[i].x), tf32r(ra[i].y), tf32r(ra[i].z), tf32r(ra[i].w));
                *(uint4*)&sdyn[nbuf * AS_F + (arow + i * 16) * APAD + akq] = v;
            }
#pragma unroll
            for (int i = 0; i < 8; i++) {
                uint4 v = make_uint4(tf32r(rb[i].x), tf32r(rb[i].y), tf32r(rb[i].z), tf32r(rb[i].w));
                *(uint4*)&sdyn[2 * AS_F + nbuf * BS_F + (arow + i * 16) * APAD + akq] = v;
            }
        }
    }

#pragma unroll
    for (int g = 0; g < 4; g++) {
        int cb = n0 + g * 32 + wn * 8 + tidg * 2;
        float2 bv = *(const float2*)(bias + cb);
#pragma unroll
        for (int mt = 0; mt < 2; mt++)
#pragma unroll
            for (int rh = 0; rh < 2; rh++) {
                int row = m0 + wm * 32 + mt * 16 + rh * 8 + gid;
                float2 o;
                o.x = acc[mt][g][rh * 2 + 0] + bv.x;
                o.y = acc[mt][g][rh * 2 + 1] + bv.y;
                if (do_relu) { o.x = fmaxf(o.x, 0.f); o.y = fmaxf(o.y, 0.f); }
                *(float2*)&C[(size_t)row * N + cb] = o;
            }
    }
}

// ---------------- persistent LSTM tile: one (m0, jb) tile, one layer ----------------
__device__ __forceinline__ void lstm_tile(
    float* sdyn, int tid, int wm, int wn, int gid, int tidg, int jb, int m0,
    const float* hA, const float* W, const float* hA2, const float* W2,
    const float* Apre, const float* bias,
    float* cS, float* hOut, float* hsOut)
{
    float acc[2][4][4];
#pragma unroll
    for (int mt = 0; mt < 2; mt++)
#pragma unroll
        for (int g = 0; g < 4; g++)
#pragma unroll
            for (int q = 0; q < 4; q++) acc[mt][g][q] = 0.f;

    int C = hA2 ? 8 : 4;
    int arow = tid >> 4, akq = (tid & 15) << 2;
    float4 ra[4], rb[8];

    // prologue: chunk 0
#pragma unroll
    for (int i = 0; i < 4; i++)
        ra[i] = ldcg4(hA + (size_t)(m0 + arow + i * 16) * HH + akq);
#pragma unroll
    for (int i = 0; i < 8; i++) {
        int row = arow + i * 16;
        int Wrow = (row >> 5) * 256 + jb + (row & 31);
        rb[i] = *(const float4*)(W + (size_t)Wrow * HH + akq);
    }
#pragma unroll
    for (int i = 0; i < 4; i++) {
        uint4 v = make_uint4(tf32r(ra[i].x), tf32r(ra[i].y), tf32r(ra[i].z), tf32r(ra[i].w));
        *(uint4*)&sdyn[(arow + i * 16) * APAD + akq] = v;
    }
#pragma unroll
    for (int i = 0; i < 8; i++) {
        uint4 v = make_uint4(tf32r(rb[i].x), tf32r(rb[i].y), tf32r(rb[i].z), tf32r(rb[i].w));
        *(uint4*)&sdyn[2 * AS_F + (arow + i * 16) * APAD + akq] = v;
    }

    for (int c = 0; c < C; c++) {
        __syncthreads();
        int buf = c & 1;
        if (c + 1 < C) {
            const float* As = (c + 1 < 4) ? hA : hA2;
            const float* Ws = (c + 1 < 4) ? W  : W2;
            int kb = ((c + 1) & 3) * KCH;
#pragma unroll
            for (int i = 0; i < 4; i++)
                ra[i] = ldcg4(As + (size_t)(m0 + arow + i * 16) * HH + kb + akq);
#pragma unroll
            for (int i = 0; i < 8; i++) {
                int row = arow + i * 16;
                int Wrow = (row >> 5) * 256 + jb + (row & 31);
                rb[i] = *(const float4*)(Ws + (size_t)Wrow * HH + kb + akq);
            }
        }
        const float* Ab = sdyn + buf * AS_F;
        const float* Bb = sdyn + 2 * AS_F + buf * BS_F;
#pragma unroll
        for (int kk = 0; kk < 8; kk++) {
            int k = kk * 8;
            uint32_t af[2][4];
#pragma unroll
            for (int mt = 0; mt < 2; mt++) {
                int rbase = wm * 32 + mt * 16;
                af[mt][0] = __float_as_uint(Ab[(rbase + gid) * APAD + k + tidg]);
                af[mt][1] = __float_as_uint(Ab[(rbase + gid + 8) * APAD + k + tidg]);
                af[mt][2] = __float_as_uint(Ab[(rbase + gid) * APAD + k + tidg + 4]);
                af[mt][3] = __float_as_uint(Ab[(rbase + gid + 8) * APAD + k + tidg + 4]);
            }
            uint32_t bf[4][2];
#pragma unroll
            for (int g = 0; g < 4; g++) {
                int n = g * 32 + wn * 8 + gid;
                bf[g][0] = __float_as_uint(Bb[n * APAD + k + tidg]);
                bf[g][1] = __float_as_uint(Bb[n * APAD + k + tidg + 4]);
            }
#pragma unroll
            for (int mt = 0; mt < 2; mt++)
#pragma unroll
                for (int g = 0; g < 4; g++)
                    mma_tf32(acc[mt][g], af[mt], bf[g]);
        }
        if (c + 1 < C) {
            int nbuf = (c + 1) & 1;
#pragma unroll
            for (int i = 0; i < 4; i++) {
                uint4 v = make_uint4(tf32r(ra[i].x), tf32r(ra[i].y), tf32r(ra[i].z), tf32r(ra[i].w));
                *(uint4*)&sdyn[nbuf * AS_F + (arow + i * 16) * APAD + akq] = v;
            }
#pragma unroll
            for (int i = 0; i < 8; i++) {
                uint4 v = make_uint4(tf32r(rb[i].x), tf32r(rb[i].y), tf32r(rb[i].z), tf32r(rb[i].w));
                *(uint4*)&sdyn[2 * AS_F + nbuf * BS_F + (arow + i * 16) * APAD + akq] = v;
            }
        }
    }

    // epilogue: fused LSTM cell
    int j2 = jb + wn * 8 + tidg * 2;
#pragma unroll
    for (int mt = 0; mt < 2; mt++)
#pragma unroll
        for (int rh = 0; rh < 2; rh++) {
            int row = m0 + wm * 32 + mt * 16 + rh * 8 + gid;
            float2 aI, aF, aG, aO;
            if (Apre) {
                const float* ap = Apre + (size_t)row * G4 + j2;
                aI = *(const float2*)(ap);
                aF = *(const float2*)(ap + 256);
                aG = *(const float2*)(ap + 512);
                aO = *(const float2*)(ap + 768);
            } else {
                aI = *(const float2*)(bias + j2);
                aF = *(const float2*)(bias + 256 + j2);
                aG = *(const float2*)(bias + 512 + j2);
                aO = *(const float2*)(bias + 768 + j2);
            }
            float2 cc = *(const float2*)(cS + (size_t)row * HH + j2);
            float2 ho, co, hs;
#pragma unroll
            for (int jj = 0; jj < 2; jj++) {
                float gi = acc[mt][0][rh * 2 + jj] + (jj ? aI.y : aI.x);
                float gf = acc[mt][1][rh * 2 + jj] + (jj ? aF.y : aF.x);
                float gG = acc[mt][2][rh * 2 + jj] + (jj ? aG.y : aG.x);
                float go = acc[mt][3][rh * 2 + jj] + (jj ? aO.y : aO.x);
                float cprev = jj ? cc.y : cc.x;
                float c2 = sigfast(gf) * cprev + sigfast(gi) * tanhfast(gG);
                float h2 = sigfast(go) * tanhfast(c2);
                if (jj) { co.y = c2; ho.y = h2; hs.y = fmaxf(h2, 0.f); }
                else    { co.x = c2; ho.x = h2; hs.x = fmaxf(h2, 0.f); }
            }
            *(float2*)(cS   + (size_t)row * HH + j2) = co;
            *(float2*)(hOut + (size_t)row * HH + j2) = ho;
            if (hsOut) *(float2*)(hsOut + (size_t)row * HH + j2) = hs;
        }
}

// ---------------- persistent sequential kernel: all 128 timesteps ----------------
__global__ __launch_bounds__(256, 1) void lstm_seq(
    const float* __restrict__ Whh0, const float* __restrict__ Wih1,
    const float* __restrict__ Whh1,
    const float* __restrict__ A0, const float* __restrict__ bias1,
    float* __restrict__ state, float* __restrict__ hs)
{
    extern __shared__ float sdyn[];
    int tid = threadIdx.x;
    int lane = tid & 31, wid = tid >> 5;
    int wm = wid >> 2, wn = wid & 3;
    int gid = lane >> 2, tidg = lane & 3;
    int jb = (blockIdx.x & 7) << 5;
    int m0 = (blockIdx.x >> 3) << 6;

    float* h0[2] = { state,               state +     BB * HH };
    float* h1[2] = { state + 2 * BB * HH, state + 3 * BB * HH };
    float* c0 = state + 4 * BB * HH;
    float* c1 = state + 5 * BB * HH;

    unsigned lp = 0;
    for (int t = 0; t < TT; t++) {
        int pi = t & 1, po = pi ^ 1;
        // layer 0: gates0 = A0[t] + h0 @ Whh0^T -> cell -> h0[po], c0
        lstm_tile(sdyn, tid, wm, wn, gid, tidg, jb, m0,
                  h0[pi], Whh0, nullptr, nullptr,
                  A0 + (size_t)t * BB * G4, nullptr,
                  c0, h0[po], nullptr);
        gsync(&lp, tid);
        // layer 1: gates1 = bias1 + h0[po]@Wih1^T + h1[pi]@Whh1^T -> h1[po], c1, hs[t]
        lstm_tile(sdyn, tid, wm, wn, gid, tidg, jb, m0,
                  h0[po], Wih1, h1[pi], Whh1,
                  nullptr, bias1,
                  c1, h1[po], hs + (size_t)t * BB * HH);
        gsync(&lp, tid);
    }
}

// ---------------- fp32 f32x2 SGEMM (out-MLP, exact) ----------------
__global__ __launch_bounds__(256) void sgemm128(
    int M, int N, int K,
    const float* __restrict__ A, const float* __restrict__ B,
    const float* __restrict__ bias1,
    float* __restrict__ C, int do_relu)
{
    __shared__ float As[8][132];
    __shared__ float Bs[8][132];
    int tid = threadIdx.x;
    int tx = tid & 15, ty = tid >> 4;
    int m0 = blockIdx.y << 7, n0 = blockIdx.x << 7;

    const float* Ald = A + (size_t)(m0 + (tid >> 1)) * K + (tid & 1) * 4;
    const float* Bld = B + (size_t)(n0 + (tid >> 1)) * K + (tid & 1) * 4;
    int kr = (tid & 1) * 4, mr = tid >> 1;

    u64 acc[4][8];
#pragma unroll
    for (int i = 0; i < 4; i++)
#pragma unroll
        for (int j = 0; j < 8; j++) acc[i][j] = 0ull;

    float4 ra = *(const float4*)Ald;
    float4 rb = *(const float4*)Bld;

    for (int k0 = 0; k0 < K; k0 += 8) {
        __syncthreads();
        As[kr+0][mr] = ra.x; As[kr+1][mr] = ra.y; As[kr+2][mr] = ra.z; As[kr+3][mr] = ra.w;
        Bs[kr+0][mr] = rb.x; Bs[kr+1][mr] = rb.y; Bs[kr+2][mr] = rb.z; Bs[kr+3][mr] = rb.w;
        __syncthreads();
        if (k0 + 8 < K) {
            ra = *(const float4*)(Ald + k0 + 8);
            rb = *(const float4*)(Bld + k0 + 8);
        }
#pragma unroll
        for (int k = 0; k < 8; k++) {
            ulonglong2 aL = *(const ulonglong2*)&As[k][ty * 4];
            ulonglong2 aH = *(const ulonglong2*)&As[k][ty * 4 + 64];
            float4 bL = *(const float4*)&Bs[k][tx * 4];
            float4 bH = *(const float4*)&Bs[k][tx * 4 + 64];
            u64 bd[8] = { dup2(bL.x), dup2(bL.y), dup2(bL.z), dup2(bL.w),
                          dup2(bH.x), dup2(bH.y), dup2(bH.z), dup2(bH.w) };
#pragma unroll
            for (int j = 0; j < 8; j++) {
                fma2(acc[0][j], aL.x, bd[j]);
                fma2(acc[1][j], aL.y, bd[j]);
                fma2(acc[2][j], aH.x, bd[j]);
                fma2(acc[3][j], aH.y, bd[j]);
            }
        }
    }

#pragma unroll
    for (int cq = 0; cq < 2; cq++) {
        int cbase = n0 + tx * 4 + cq * 64;
        float4 bv = *(const float4*)&bias1[cbase];
#pragma unroll
        for (int rq = 0; rq < 2; rq++)
#pragma unroll
            for (int p = 0; p < 2; p++) {
                int rp = rq * 2 + p;
#pragma unroll
                for (int h = 0; h < 2; h++) {
                    int row = m0 + ty * 4 + rq * 64 + 2 * p + h;
                    float4 o;
                    o.x = (h ? hi32(acc[rp][cq*4+0]) : lo32(acc[rp][cq*4+0])) + bv.x;
                    o.y = (h ? hi32(acc[rp][cq*4+1]) : lo32(acc[rp][cq*4+1])) + bv.y;
                    o.z = (h ? hi32(acc[rp][cq*4+2]) : lo32(acc[rp][cq*4+2])) + bv.z;
                    o.w = (h ? hi32(acc[rp][cq*4+3]) : lo32(acc[rp][cq*4+3])) + bv.w;
                    if (do_relu) {
                        o.x = fmaxf(o.x, 0.f); o.y = fmaxf(o.y, 0.f);
                        o.z = fmaxf(o.z, 0.f); o.w = fmaxf(o.w, 0.f);
                    }
                    *(float4*)&C[(size_t)row * N + cbase] = o;
                }
            }
    }
}

// ---------------- output final layer ----------------
__global__ void out_mlp_warp(const float* __restrict__ Y, const float* __restrict__ W,
                             const float* __restrict__ b, float* __restrict__ out) {
    int warp = (blockIdx.x * blockDim.x + threadIdx.x) >> 5;
    int lane = threadIdx.x & 31;
    const float* yr = Y + (size_t)warp * HH;
    float y[8];
#pragma unroll
    for (int i = 0; i < 8; i++) y[i] = yr[lane + 32 * i];
#pragma unroll
    for (int n = 0; n < 6; n++) {
        const float* wr = W + n * HH;
        float s = 0.f;
#pragma unroll
        for (int i = 0; i < 8; i++) s = fmaf(y[i], wr[lane + 32 * i], s);
#pragma unroll
        for (int off = 16; off; off >>= 1) s += __shfl_xor_sync(0xffffffffu, s, off);
        if (lane == 0) out[(size_t)warp * 6 + n] = s + b[n];
    }
}

// ---------------- launch ----------------
extern "C" void kernel_launch(void* const* d_in, const int* in_sizes, int n_in,
                              void* d_out, int out_size) {
    const float* x    = (const float*)d_in[0];
    const float* Wi1  = (const float*)d_in[1];
    const float* bi1  = (const float*)d_in[2];
    const float* Wi2  = (const float*)d_in[3];
    const float* bi2  = (const float*)d_in[4];
    const float* Wi3  = (const float*)d_in[5];
    const float* bi3  = (const float*)d_in[6];
    const float* Wih0 = (const float*)d_in[7];
    const float* Whh0 = (const float*)d_in[8];
    const float* bih0 = (const float*)d_in[9];
    const float* bhh0 = (const float*)d_in[10];
    const float* Wih1 = (const float*)d_in[11];
    const float* Whh1 = (const float*)d_in[12];
    const float* bih1 = (const float*)d_in[13];
    const float* bhh1 = (const float*)d_in[14];
    const float* Wo1  = (const float*)d_in[15];
    const float* bo1  = (const float*)d_in[16];
    const float* Wo2  = (const float*)d_in[17];
    const float* bo2  = (const float*)d_in[18];
    const float* Wo3  = (const float*)d_in[19];
    const float* bo3  = (const float*)d_in[20];
    float* out = (float*)d_out;

    float *bufA, *bufB, *bufC, *A0, *state, *bias1, *bias0;
    cudaGetSymbolAddress((void**)&bufA, g_bufA);
    cudaGetSymbolAddress((void**)&bufB, g_bufB);
    cudaGetSymbolAddress((void**)&bufC, g_bufC);
    cudaGetSymbolAddress((void**)&A0, g_A0);
    cudaGetSymbolAddress((void**)&state, g_state);
    cudaGetSymbolAddress((void**)&bias1, g_bias1);
    cudaGetSymbolAddress((void**)&bias0, g_bias0);

    cudaFuncSetAttribute(gemm_mma, cudaFuncAttributeMaxDynamicSharedMemorySize, SMEM_MMA);
    cudaFuncSetAttribute(lstm_seq, cudaFuncAttributeMaxDynamicSharedMemorySize, SMEM_MMA);

    // ---- parallel phase ----
    in_mlp1<<<TB * HH / 256, 256>>>(x, Wi1, bi1, bufA);
    gemm_mma<<<dim3(2, TB / 64), 256, SMEM_MMA>>>(HH, HH, bufA, Wi2, bi2, bufB, 1);
    gemm_mma<<<dim3(2, TB / 64), 256, SMEM_MMA>>>(HH, HH, bufB, Wi3, bi3, bufC, 1);
    bias_comb<<<G4 / 256, 256>>>(bih0, bhh0, bias0);
    gemm_mma<<<dim3(8, TB / 64), 256, SMEM_MMA>>>(G4, HH, bufC, Wih0, bias0, A0, 0);

    zero6<<<(6 * BB * HH / 4) / 256, 256>>>(state);
    bias_comb<<<G4 / 256, 256>>>(bih1, bhh1, bias1);

    // ---- sequential phase: ONE persistent kernel, 128 steps, grid barriers ----
    lstm_seq<<<128, 256, SMEM_MMA>>>(Whh0, Wih1, Whh1, A0, bias1, state, bufA);

    // ---- output MLP: exact fp32 (error margin) ----
    sgemm128<<<dim3(2, TB / 128), 256>>>(TB, HH, HH, bufA, Wo1, bo1, bufB, 1);
    sgemm128<<<dim3(2, TB / 128), 256>>>(TB, HH, HH, bufB, Wo2, bo2, bufC, 1);
    out_mlp_warp<<<TB / 8, 256>>>(bufC, Wo3, bo3, out);
}

// round 12
// speedup vs baseline: 1.0836x; 1.0836x over previous
#include <cuda_runtime.h>
#include <math.h>
#include <cstdint>

#define TT 128
#define BB 1024
#define HH 256
#define G4 1024
#define TB (TT*BB)

typedef unsigned long long u64;

// ---------------- scratch (allocation-free) ----------------
__device__ float g_bufA[(size_t)TB*HH];   // hs (relu h1) history
__device__ float g_bufB[(size_t)TB*HH];   // h0 history
__device__ float g_bufC[(size_t)TB*HH];
__device__ float g_A0[(size_t)TB*G4];     // A0 then A1 (reused)
__device__ float g_state[6*BB*HH];
__device__ float g_bias1[G4];
__device__ float g_bias0[G4];
__device__ unsigned g_bar;
__device__ unsigned g_phase_ctr;

// ---------------- f32x2 helpers (fp32 out-MLP) ----------------
__device__ __forceinline__ void fma2(u64 &d, u64 a, u64 b) {
    asm("fma.rn.f32x2 %0, %1, %2, %0;" : "+l"(d) : "l"(a), "l"(b));
}
__device__ __forceinline__ u64 dup2(float x) {
    u64 r; asm("mov.b64 %0, {%1, %1};" : "=l"(r) : "f"(x)); return r;
}
__device__ __forceinline__ float lo32(u64 v) {
    float f; asm("{ .reg .b32 t; mov.b64 {%0, t}, %1; }" : "=f"(f) : "l"(v)); return f;
}
__device__ __forceinline__ float hi32(u64 v) {
    float f; asm("{ .reg .b32 t; mov.b64 {t, %0}, %1; }" : "=f"(f) : "l"(v)); return f;
}

// ---------------- tf32 / activation helpers ----------------
__device__ __forceinline__ uint32_t tf32r(float x) {
    uint32_t r; asm("cvt.rna.tf32.f32 %0, %1;" : "=r"(r) : "f"(x)); return r;
}
__device__ __forceinline__ float tanhfast(float x) {
    float r; asm("tanh.approx.f32 %0, %1;" : "=f"(r) : "f"(x)); return r;
}
__device__ __forceinline__ float sigfast(float x) {
    return fmaf(tanhfast(0.5f * x), 0.5f, 0.5f);
}
__device__ __forceinline__ void mma_tf32(float* d, const uint32_t* a, const uint32_t* b) {
    asm volatile(
        "mma.sync.aligned.m16n8k8.row.col.f32.tf32.tf32.f32 "
        "{%0,%1,%2,%3}, {%4,%5,%6,%7}, {%8,%9}, {%0,%1,%2,%3};"
        : "+f"(d[0]), "+f"(d[1]), "+f"(d[2]), "+f"(d[3])
        : "r"(a[0]), "r"(a[1]), "r"(a[2]), "r"(a[3]), "r"(b[0]), "r"(b[1]));
}
__device__ __forceinline__ float4 ldcg4(const float* p) {
    return __ldcg((const float4*)p);
}

// ---------------- grid barrier (128 CTAs) ----------------
__device__ __forceinline__ void gsync(unsigned* lp, int tid) {
    __syncthreads();
    if (tid == 0) {
        __threadfence();
        unsigned old = atomicAdd(&g_bar, 1u);
        if (old == 127u) {
            g_bar = 0u;
            __threadfence();
            atomicAdd(&g_phase_ctr, 1u);
        } else {
            while (*(volatile unsigned*)&g_phase_ctr <= *lp) __nanosleep(64);
        }
    }
    (*lp)++;
    __syncthreads();
}

// ---------------- small kernels ----------------
__global__ void zero6(float* s) {
    int i = blockIdx.x * blockDim.x + threadIdx.x;
    ((float4*)s)[i] = make_float4(0.f, 0.f, 0.f, 0.f);
    if (i == 0) { g_bar = 0u; g_phase_ctr = 0u; }
}
__global__ void bias_comb(const float* a, const float* b, float* o) {
    int i = blockIdx.x * blockDim.x + threadIdx.x;
    o[i] = a[i] + b[i];
}
__global__ void in_mlp1(const float* __restrict__ x, const float* __restrict__ W,
                        const float* __restrict__ b, float* __restrict__ out) {
    int idx = blockIdx.x * blockDim.x + threadIdx.x;
    int m = idx >> 8, n = idx & 255;
    const float* xr = x + m * 6;
    const float* wr = W + n * 6;
    float s = b[n];
#pragma unroll
    for (int k = 0; k < 6; k++) s = fmaf(xr[k], wr[k], s);
    out[idx] = fmaxf(s, 0.f);
}

// ---------------- smem configs ----------------
#define APAD 68
#define AS_F (64*APAD)
#define BS_F (128*APAD)
#define SMEM_MMA ((2*AS_F + 2*BS_F)*4)
// persistent: 4 resident W chunks + 2 A buffers
#define SMEMP ((4*BS_F + 2*AS_F)*4)

// ---------------- generic tf32 mma GEMM: C = act(A@B^T + bias) ----------------
__global__ __launch_bounds__(256, 1) void gemm_mma(
    int N, int K,
    const float* __restrict__ A, const float* __restrict__ B,
    const float* __restrict__ bias, float* __restrict__ C, int do_relu)
{
    extern __shared__ float sdyn[];
    int tid = threadIdx.x;
    int lane = tid & 31, wid = tid >> 5;
    int wm = wid >> 2, wn = wid & 3;
    int gid = lane >> 2, tidg = lane & 3;
    int n0 = blockIdx.x << 7;
    int m0 = blockIdx.y << 6;

    float acc[2][4][4];
#pragma unroll
    for (int mt = 0; mt < 2; mt++)
#pragma unroll
        for (int g = 0; g < 4; g++)
#pragma unroll
            for (int q = 0; q < 4; q++) acc[mt][g][q] = 0.f;

    int CH = K >> 6;
    int arow = tid >> 4, akq = (tid & 15) << 2;
    float4 ra[4], rb[8];

#pragma unroll
    for (int i = 0; i < 4; i++)
        ra[i] = *(const float4*)(A + (size_t)(m0 + arow + i * 16) * K + akq);
#pragma unroll
    for (int i = 0; i < 8; i++)
        rb[i] = *(const float4*)(B + (size_t)(n0 + arow + i * 16) * K + akq);
#pragma unroll
    for (int i = 0; i < 4; i++) {
        uint4 v = make_uint4(tf32r(ra[i].x), tf32r(ra[i].y), tf32r(ra[i].z), tf32r(ra[i].w));
        *(uint4*)&sdyn[(arow + i * 16) * APAD + akq] = v;
    }
#pragma unroll
    for (int i = 0; i < 8; i++) {
        uint4 v = make_uint4(tf32r(rb[i].x), tf32r(rb[i].y), tf32r(rb[i].z), tf32r(rb[i].w));
        *(uint4*)&sdyn[2 * AS_F + (arow + i * 16) * APAD + akq] = v;
    }

    for (int c = 0; c < CH; c++) {
        __syncthreads();
        int buf = c & 1;
        if (c + 1 < CH) {
            int kb = (c + 1) << 6;
#pragma unroll
            for (int i = 0; i < 4; i++)
                ra[i] = *(const float4*)(A + (size_t)(m0 + arow + i * 16) * K + kb + akq);
#pragma unroll
            for (int i = 0; i < 8; i++)
                rb[i] = *(const float4*)(B + (size_t)(n0 + arow + i * 16) * K + kb + akq);
        }
        const float* Ab = sdyn + buf * AS_F;
        const float* Bb = sdyn + 2 * AS_F + buf * BS_F;
#pragma unroll
        for (int kk = 0; kk < 8; kk++) {
            int k = kk * 8;
            uint32_t af[2][4];
#pragma unroll
            for (int mt = 0; mt < 2; mt++) {
                int rbase = wm * 32 + mt * 16;
                af[mt][0] = __float_as_uint(Ab[(rbase + gid) * APAD + k + tidg]);
                af[mt][1] = __float_as_uint(Ab[(rbase + gid + 8) * APAD + k + tidg]);
                af[mt][2] = __float_as_uint(Ab[(rbase + gid) * APAD + k + tidg + 4]);
                af[mt][3] = __float_as_uint(Ab[(rbase + gid + 8) * APAD + k + tidg + 4]);
            }
            uint32_t bf[4][2];
#pragma unroll
            for (int g = 0; g < 4; g++) {
                int n = g * 32 + wn * 8 + gid;
                bf[g][0] = __float_as_uint(Bb[n * APAD + k + tidg]);
                bf[g][1] = __float_as_uint(Bb[n * APAD + k + tidg + 4]);
            }
#pragma unroll
            for (int mt = 0; mt < 2; mt++)
#pragma unroll
                for (int g = 0; g < 4; g++)
                    mma_tf32(acc[mt][g], af[mt], bf[g]);
        }
        if (c + 1 < CH) {
            int nbuf = (c + 1) & 1;
#pragma unroll
            for (int i = 0; i < 4; i++) {
                uint4 v = make_uint4(tf32r(ra[i].x), tf32r(ra[i].y), tf32r(ra[i].z), tf32r(ra[i].w));
                *(uint4*)&sdyn[nbuf * AS_F + (arow + i * 16) * APAD + akq] = v;
            }
#pragma unroll
            for (int i = 0; i < 8; i++) {
                uint4 v = make_uint4(tf32r(rb[i].x), tf32r(rb[i].y), tf32r(rb[i].z), tf32r(rb[i].w));
                *(uint4*)&sdyn[2 * AS_F + nbuf * BS_F + (arow + i * 16) * APAD + akq] = v;
            }
        }
    }

#pragma unroll
    for (int g = 0; g < 4; g++) {
        int cb = n0 + g * 32 + wn * 8 + tidg * 2;
        float2 bv = *(const float2*)(bias + cb);
#pragma unroll
        for (int mt = 0; mt < 2; mt++)
#pragma unroll
            for (int rh = 0; rh < 2; rh++) {
                int row = m0 + wm * 32 + mt * 16 + rh * 8 + gid;
                float2 o;
                o.x = acc[mt][g][rh * 2 + 0] + bv.x;
                o.y = acc[mt][g][rh * 2 + 1] + bv.y;
                if (do_relu) { o.x = fmaxf(o.x, 0.f); o.y = fmaxf(o.y, 0.f); }
                *(float2*)&C[(size_t)row * N + cb] = o;
            }
    }
}

// ---------------- persistent single-layer LSTM pass ----------------
// 128 CTAs (16 m-tiles x 8 j-tiles), weights RESIDENT in smem, 128 phases.
// gates[t] = Apre[t] + hIn[t] @ W^T ; cell -> cS, hOut[t] (+ optional relu hs).
// hHist != null: history mode (hIn = hHist[t-1] or zeros, hOut = hHist[t]).
// else: ping-pong p0/p1.
__global__ __launch_bounds__(256, 1) void lstm_persist(
    const float* __restrict__ W,
    const float* __restrict__ Apre,
    float* __restrict__ hHist,
    float* __restrict__ p0, float* __restrict__ p1,
    float* __restrict__ cS,
    float* __restrict__ hsBase)
{
    extern __shared__ float sm[];
    float* sW = sm;               // 4 chunks x [128][APAD]
    float* sA = sm + 4 * BS_F;    // 2 bufs x [64][APAD]

    int tid = threadIdx.x;
    int lane = tid & 31, wid = tid >> 5;
    int wm = wid >> 2, wn = wid & 3;
    int gid = lane >> 2, tidg = lane & 3;
    int jb = (blockIdx.x & 7) << 5;
    int m0 = (blockIdx.x >> 3) << 6;

    // ---- load resident weights (once): 4 chunks x 128 rows x 64 k ----
    {
        int rr = tid >> 4;
        int kq = (tid & 15) << 2;
        for (int c = 0; c < 4; c++)
#pragma unroll
            for (int i = 0; i < 8; i++) {
                int row = rr + i * 16;
                int Wrow = (row >> 5) * 256 + jb + (row & 31);
                float4 v = *(const float4*)(W + (size_t)Wrow * HH + c * 64 + kq);
                uint4 u = make_uint4(tf32r(v.x), tf32r(v.y), tf32r(v.z), tf32r(v.w));
                *(uint4*)&sW[c * BS_F + row * APAD + kq] = u;
            }
    }
    __syncthreads();

    unsigned lp = *(volatile unsigned*)&g_phase_ctr;

    int arow = tid >> 4, akq = (tid & 15) << 2;
    int j2 = jb + wn * 8 + tidg * 2;

    for (int t = 0; t < TT; t++) {
        const float* hIn;
        float* hOut;
        if (hHist) {
            hIn  = t ? hHist + (size_t)(t - 1) * BB * HH : p0;
            hOut = hHist + (size_t)t * BB * HH;
        } else {
            hIn  = (t & 1) ? p1 : p0;
            hOut = (t & 1) ? p0 : p1;
        }

        // early-issue Apre loads (hidden behind MMA loop)
        float2 apre[4][4];
        {
            const float* base = Apre + (size_t)t * BB * G4;
#pragma unroll
            for (int mt = 0; mt < 2; mt++)
#pragma unroll
                for (int rh = 0; rh < 2; rh++) {
                    int row = m0 + wm * 32 + mt * 16 + rh * 8 + gid;
                    const float* ap = base + (size_t)row * G4 + j2;
                    apre[mt * 2 + rh][0] = *(const float2*)(ap);
                    apre[mt * 2 + rh][1] = *(const float2*)(ap + 256);
                    apre[mt * 2 + rh][2] = *(const float2*)(ap + 512);
                    apre[mt * 2 + rh][3] = *(const float2*)(ap + 768);
                }
        }

        float acc[2][4][4];
#pragma unroll
        for (int mt = 0; mt < 2; mt++)
#pragma unroll
            for (int g = 0; g < 4; g++)
#pragma unroll
                for (int q = 0; q < 4; q++) acc[mt][g][q] = 0.f;

        // stage A chunk 0
        float4 ra[4];
#pragma unroll
        for (int i = 0; i < 4; i++)
            ra[i] = ldcg4(hIn + (size_t)(m0 + arow + i * 16) * HH + akq);
#pragma unroll
        for (int i = 0; i < 4; i++) {
            uint4 u = make_uint4(tf32r(ra[i].x), tf32r(ra[i].y), tf32r(ra[i].z), tf32r(ra[i].w));
            *(uint4*)&sA[(arow + i * 16) * APAD + akq] = u;
        }

        for (int c = 0; c < 4; c++) {
            __syncthreads();
            int buf = c & 1;
            if (c < 3) {
                int kb = (c + 1) << 6;
#pragma unroll
                for (int i = 0; i < 4; i++)
                    ra[i] = ldcg4(hIn + (size_t)(m0 + arow + i * 16) * HH + kb + akq);
            }
            const float* Ab = sA + buf * AS_F;
            const float* Bb = sW + c * BS_F;
#pragma unroll
            for (int kk = 0; kk < 8; kk++) {
                int k = kk * 8;
                uint32_t af[2][4];
#pragma unroll
                for (int mt = 0; mt < 2; mt++) {
                    int rbase = wm * 32 + mt * 16;
                    af[mt][0] = __float_as_uint(Ab[(rbase + gid) * APAD + k + tidg]);
                    af[mt][1] = __float_as_uint(Ab[(rbase + gid + 8) * APAD + k + tidg]);
                    af[mt][2] = __float_as_uint(Ab[(rbase + gid) * APAD + k + tidg + 4]);
                    af[mt][3] = __float_as_uint(Ab[(rbase + gid + 8) * APAD + k + tidg + 4]);
                }
                uint32_t bf[4][2];
#pragma unroll
                for (int g = 0; g < 4; g++) {
                    int n = g * 32 + wn * 8 + gid;
                    bf[g][0] = __float_as_uint(Bb[n * APAD + k + tidg]);
                    bf[g][1] = __float_as_uint(Bb[n * APAD + k + tidg + 4]);
                }
#pragma unroll
                for (int mt = 0; mt < 2; mt++)
#pragma unroll
                    for (int g = 0; g < 4; g++)
                        mma_tf32(acc[mt][g], af[mt], bf[g]);
            }
            if (c < 3) {
                int nbuf = (c + 1) & 1;
#pragma unroll
                for (int i = 0; i < 4; i++) {
                    uint4 u = make_uint4(tf32r(ra[i].x), tf32r(ra[i].y), tf32r(ra[i].z), tf32r(ra[i].w));
                    *(uint4*)&sA[nbuf * AS_F + (arow + i * 16) * APAD + akq] = u;
                }
            }
        }

        // epilogue: fused LSTM cell
#pragma unroll
        for (int mt = 0; mt < 2; mt++)
#pragma unroll
            for (int rh = 0; rh < 2; rh++) {
                int row = m0 + wm * 32 + mt * 16 + rh * 8 + gid;
                float2 aI = apre[mt * 2 + rh][0];
                float2 aF = apre[mt * 2 + rh][1];
                float2 aG = apre[mt * 2 + rh][2];
                float2 aO = apre[mt * 2 + rh][3];
                float2 cc = *(const float2*)(cS + (size_t)row * HH + j2);
                float2 ho, co, hs;
#pragma unroll
                for (int jj = 0; jj < 2; jj++) {
                    float gi = acc[mt][0][rh * 2 + jj] + (jj ? aI.y : aI.x);
                    float gf = acc[mt][1][rh * 2 + jj] + (jj ? aF.y : aF.x);
                    float gG = acc[mt][2][rh * 2 + jj] + (jj ? aG.y : aG.x);
                    float go = acc[mt][3][rh * 2 + jj] + (jj ? aO.y : aO.x);
                    float cprev = jj ? cc.y : cc.x;
                    float c2 = sigfast(gf) * cprev + sigfast(gi) * tanhfast(gG);
                    float h2 = sigfast(go) * tanhfast(c2);
                    if (jj) { co.y = c2; ho.y = h2; hs.y = fmaxf(h2, 0.f); }
                    else    { co.x = c2; ho.x = h2; hs.x = fmaxf(h2, 0.f); }
                }
                *(float2*)(cS   + (size_t)row * HH + j2) = co;
                *(float2*)(hOut + (size_t)row * HH + j2) = ho;
                if (hsBase) *(float2*)(hsBase + (size_t)t * BB * HH + (size_t)row * HH + j2) = hs;
            }

        gsync(&lp, tid);
    }
}

// ---------------- fp32 f32x2 SGEMM (out-MLP, exact) ----------------
__global__ __launch_bounds__(256) void sgemm128(
    int M, int N, int K,
    const float* __restrict__ A, const float* __restrict__ B,
    const float* __restrict__ bias1,
    float* __restrict__ C, int do_relu)
{
    __shared__ float As[8][132];
    __shared__ float Bs[8][132];
    int tid = threadIdx.x;
    int tx = tid & 15, ty = tid >> 4;
    int m0 = blockIdx.y << 7, n0 = blockIdx.x << 7;

    const float* Ald = A + (size_t)(m0 + (tid >> 1)) * K + (tid & 1) * 4;
    const float* Bld = B + (size_t)(n0 + (tid >> 1)) * K + (tid & 1) * 4;
    int kr = (tid & 1) * 4, mr = tid >> 1;

    u64 acc[4][8];
#pragma unroll
    for (int i = 0; i < 4; i++)
#pragma unroll
        for (int j = 0; j < 8; j++) acc[i][j] = 0ull;

    float4 ra = *(const float4*)Ald;
    float4 rb = *(const float4*)Bld;

    for (int k0 = 0; k0 < K; k0 += 8) {
        __syncthreads();
        As[kr+0][mr] = ra.x; As[kr+1][mr] = ra.y; As[kr+2][mr] = ra.z; As[kr+3][mr] = ra.w;
        Bs[kr+0][mr] = rb.x; Bs[kr+1][mr] = rb.y; Bs[kr+2][mr] = rb.z; Bs[kr+3][mr] = rb.w;
        __syncthreads();
        if (k0 + 8 < K) {
            ra = *(const float4*)(Ald + k0 + 8);
            rb = *(const float4*)(Bld + k0 + 8);
        }
#pragma unroll
        for (int k = 0; k < 8; k++) {
            ulonglong2 aL = *(const ulonglong2*)&As[k][ty * 4];
            ulonglong2 aH = *(const ulonglong2*)&As[k][ty * 4 + 64];
            float4 bL = *(const float4*)&Bs[k][tx * 4];
            float4 bH = *(const float4*)&Bs[k][tx * 4 + 64];
            u64 bd[8] = { dup2(bL.x), dup2(bL.y), dup2(bL.z), dup2(bL.w),
                          dup2(bH.x), dup2(bH.y), dup2(bH.z), dup2(bH.w) };
#pragma unroll
            for (int j = 0; j < 8; j++) {
                fma2(acc[0][j], aL.x, bd[j]);
                fma2(acc[1][j], aL.y, bd[j]);
                fma2(acc[2][j], aH.x, bd[j]);
                fma2(acc[3][j], aH.y, bd[j]);
            }
        }
    }

#pragma unroll
    for (int cq = 0; cq < 2; cq++) {
        int cbase = n0 + tx * 4 + cq * 64;
        float4 bv = *(const float4*)&bias1[cbase];
#pragma unroll
        for (int rq = 0; rq < 2; rq++)
#pragma unroll
            for (int p = 0; p < 2; p++) {
                int rp = rq * 2 + p;
#pragma unroll
                for (int h = 0; h < 2; h++) {
                    int row = m0 + ty * 4 + rq * 64 + 2 * p + h;
                    float4 o;
                    o.x = (h ? hi32(acc[rp][cq*4+0]) : lo32(acc[rp][cq*4+0])) + bv.x;
                    o.y = (h ? hi32(acc[rp][cq*4+1]) : lo32(acc[rp][cq*4+1])) + bv.y;
                    o.z = (h ? hi32(acc[rp][cq*4+2]) : lo32(acc[rp][cq*4+2])) + bv.z;
                    o.w = (h ? hi32(acc[rp][cq*4+3]) : lo32(acc[rp][cq*4+3])) + bv.w;
                    if (do_relu) {
                        o.x = fmaxf(o.x, 0.f); o.y = fmaxf(o.y, 0.f);
                        o.z = fmaxf(o.z, 0.f); o.w = fmaxf(o.w, 0.f);
                    }
                    *(float4*)&C[(size_t)row * N + cbase] = o;
                }
            }
    }
}

// ---------------- output final layer ----------------
__global__ void out_mlp_warp(const float* __restrict__ Y, const float* __restrict__ W,
                             const float* __restrict__ b, float* __restrict__ out) {
    int warp = (blockIdx.x * blockDim.x + threadIdx.x) >> 5;
    int lane = threadIdx.x & 31;
    const float* yr = Y + (size_t)warp * HH;
    float y[8];
#pragma unroll
    for (int i = 0; i < 8; i++) y[i] = yr[lane + 32 * i];
#pragma unroll
    for (int n = 0; n < 6; n++) {
        const float* wr = W + n * HH;
        float s = 0.f;
#pragma unroll
        for (int i = 0; i < 8; i++) s = fmaf(y[i], wr[lane + 32 * i], s);
#pragma unroll
        for (int off = 16; off; off >>= 1) s += __shfl_xor_sync(0xffffffffu, s, off);
        if (lane == 0) out[(size_t)warp * 6 + n] = s + b[n];
    }
}

// ---------------- launch ----------------
extern "C" void kernel_launch(void* const* d_in, const int* in_sizes, int n_in,
                              void* d_out, int out_size) {
    const float* x    = (const float*)d_in[0];
    const float* Wi1  = (const float*)d_in[1];
    const float* bi1  = (const float*)d_in[2];
    const float* Wi2  = (const float*)d_in[3];
    const float* bi2  = (const float*)d_in[4];
    const float* Wi3  = (const float*)d_in[5];
    const float* bi3  = (const float*)d_in[6];
    const float* Wih0 = (const float*)d_in[7];
    const float* Whh0 = (const float*)d_in[8];
    const float* bih0 = (const float*)d_in[9];
    const float* bhh0 = (const float*)d_in[10];
    const float* Wih1 = (const float*)d_in[11];
    const float* Whh1 = (const float*)d_in[12];
    const float* bih1 = (const float*)d_in[13];
    const float* bhh1 = (const float*)d_in[14];
    const float* Wo1  = (const float*)d_in[15];
    const float* bo1  = (const float*)d_in[16];
    const float* Wo2  = (const float*)d_in[17];
    const float* bo2  = (const float*)d_in[18];
    const float* Wo3  = (const float*)d_in[19];
    const float* bo3  = (const float*)d_in[20];
    float* out = (float*)d_out;

    float *bufA, *bufB, *bufC, *A0, *state, *bias1, *bias0;
    cudaGetSymbolAddress((void**)&bufA, g_bufA);
    cudaGetSymbolAddress((void**)&bufB, g_bufB);
    cudaGetSymbolAddress((void**)&bufC, g_bufC);
    cudaGetSymbolAddress((void**)&A0, g_A0);
    cudaGetSymbolAddress((void**)&state, g_state);
    cudaGetSymbolAddress((void**)&bias1, g_bias1);
    cudaGetSymbolAddress((void**)&bias0, g_bias0);

    cudaFuncSetAttribute(gemm_mma, cudaFuncAttributeMaxDynamicSharedMemorySize, SMEM_MMA);
    cudaFuncSetAttribute(lstm_persist, cudaFuncAttributeMaxDynamicSharedMemorySize, SMEMP);

    float* zeroblk = state;                 // slot 0: zeros (pass1 h[-1], pass2 pp0)
    float* pp1     = state + BB * HH;       // slot 1: pingpong partner
    float* c0      = state + 4 * BB * HH;
    float* c1      = state + 5 * BB * HH;

    // ---- parallel phase (tf32 mma) ----
    in_mlp1<<<TB * HH / 256, 256>>>(x, Wi1, bi1, bufA);
    gemm_mma<<<dim3(2, TB / 64), 256, SMEM_MMA>>>(HH, HH, bufA, Wi2, bi2, bufB, 1);
    gemm_mma<<<dim3(2, TB / 64), 256, SMEM_MMA>>>(HH, HH, bufB, Wi3, bi3, bufC, 1);
    bias_comb<<<G4 / 256, 256>>>(bih0, bhh0, bias0);
    gemm_mma<<<dim3(8, TB / 64), 256, SMEM_MMA>>>(G4, HH, bufC, Wih0, bias0, A0, 0);

    zero6<<<(6 * BB * HH / 4) / 256, 256>>>(state);
    bias_comb<<<G4 / 256, 256>>>(bih1, bhh1, bias1);

    // ---- pass 1: persistent layer-0, stores h0 history into bufB ----
    lstm_persist<<<128, 256, SMEMP>>>(Whh0, A0, bufB, zeroblk, nullptr, c0, nullptr);

    // ---- A1 = H0 @ Wih1^T + bias1 (parallel, reuses A0 buffer) ----
    gemm_mma<<<dim3(8, TB / 64), 256, SMEM_MMA>>>(G4, HH, bufB, Wih1, bias1, A0, 0);

    // ---- pass 2: persistent layer-1, ping-pong h1, stores relu(h1) to bufA ----
    lstm_persist<<<128, 256, SMEMP>>>(Whh1, A0, nullptr, zeroblk, pp1, c1, bufA);

    // ---- output MLP: exact fp32 ----
    sgemm128<<<dim3(2, TB / 128), 256>>>(TB, HH, HH, bufA, Wo1, bo1, bufB, 1);
    sgemm128<<<dim3(2, TB / 128), 256>>>(TB, HH, HH, bufB, Wo2, bo2, bufC, 1);
    out_mlp_warp<<<TB / 8, 256>>>(bufC, Wo3, bo3, out);
}